// round 2
// baseline (speedup 1.0000x reference)
#include <cuda_runtime.h>
#include <math.h>

#define TT 2048
#define CC 2048
#define QKVD 3072
#define SP 68   // smem row stride (padding)

__device__ float g_qkv[TT * QKVD];    // [t][3072]
__device__ float g_yattn[TT * CC];    // [t][h*64+d]

// ---------------------------------------------------------------------------
// C[m][n] = sum_k A[m][k] * B[n][k] + bias[n]
// A: MxK row-major, B: NxK row-major (i.e. C = A @ B^T + bias)
// Block tile 128x128, K-step 8, 256 threads, 8x8 register tile per thread.
// ---------------------------------------------------------------------------
__global__ __launch_bounds__(256) void sgemm_nt_bias(
    const float* __restrict__ A, const float* __restrict__ B,
    const float* __restrict__ bias, float* __restrict__ C,
    int M, int N, int K)
{
    __shared__ float As[8][128];
    __shared__ float Bs[8][128];

    const int bm = blockIdx.y * 128;
    const int bn = blockIdx.x * 128;
    const int tid = threadIdx.x;
    const int tx = tid & 15;       // 0..15  -> 8 cols
    const int ty = tid >> 4;       // 0..15  -> 8 rows
    const int lr = tid >> 1;       // load row 0..127
    const int lc = (tid & 1) << 2; // load k offset 0 or 4

    const float* Aptr = A + (size_t)(bm + lr) * K + lc;
    const float* Bptr = B + (size_t)(bn + lr) * K + lc;

    float acc[8][8];
#pragma unroll
    for (int i = 0; i < 8; i++)
#pragma unroll
        for (int j = 0; j < 8; j++) acc[i][j] = 0.f;

    for (int k0 = 0; k0 < K; k0 += 8) {
        float4 av = *(const float4*)(Aptr + k0);
        float4 bv = *(const float4*)(Bptr + k0);
        As[lc + 0][lr] = av.x; As[lc + 1][lr] = av.y;
        As[lc + 2][lr] = av.z; As[lc + 3][lr] = av.w;
        Bs[lc + 0][lr] = bv.x; Bs[lc + 1][lr] = bv.y;
        Bs[lc + 2][lr] = bv.z; Bs[lc + 3][lr] = bv.w;
        __syncthreads();

#pragma unroll
        for (int kk = 0; kk < 8; kk++) {
            float4 a0 = *(const float4*)&As[kk][ty * 8];
            float4 a1 = *(const float4*)&As[kk][ty * 8 + 4];
            float4 b0 = *(const float4*)&Bs[kk][tx * 8];
            float4 b1 = *(const float4*)&Bs[kk][tx * 8 + 4];
            float ra[8] = {a0.x, a0.y, a0.z, a0.w, a1.x, a1.y, a1.z, a1.w};
            float rb[8] = {b0.x, b0.y, b0.z, b0.w, b1.x, b1.y, b1.z, b1.w};
#pragma unroll
            for (int i = 0; i < 8; i++)
#pragma unroll
                for (int j = 0; j < 8; j++)
                    acc[i][j] = fmaf(ra[i], rb[j], acc[i][j]);
        }
        __syncthreads();
    }

#pragma unroll
    for (int i = 0; i < 8; i++) {
        const int row = bm + ty * 8 + i;
#pragma unroll
        for (int j = 0; j < 8; j += 4) {
            const int col = bn + tx * 8 + j;
            float4 o;
            o.x = acc[i][j + 0] + bias[col + 0];
            o.y = acc[i][j + 1] + bias[col + 1];
            o.z = acc[i][j + 2] + bias[col + 2];
            o.w = acc[i][j + 3] + bias[col + 3];
            *(float4*)(C + (size_t)row * N + col) = o;
        }
    }
}

// ---------------------------------------------------------------------------
// In-place RoPE on first 16 dims of every Q head (32) and K group (8).
// 2048 tokens * 40 rows * 8 pairs.
// ---------------------------------------------------------------------------
__global__ __launch_bounds__(256) void rope_kernel(
    const float* __restrict__ cosb, const float* __restrict__ sinb)
{
    int idx = blockIdx.x * blockDim.x + threadIdx.x;
    const int total = TT * 40 * 8;
    if (idx >= total) return;
    int d = idx & 7;
    int row = (idx >> 3) % 40;
    int t = idx / (8 * 40);
    int off;
    if (row < 32) { int g = row >> 2, s = row & 3; off = g * 384 + s * 64; }
    else          { int g = row - 32;              off = g * 384 + 256;    }
    float* p = g_qkv + (size_t)t * QKVD + off;
    float x1 = p[d], x2 = p[d + 8];
    float c1 = cosb[t * 16 + d],     s1 = sinb[t * 16 + d];
    float c2 = cosb[t * 16 + d + 8], s2 = sinb[t * 16 + d + 8];
    p[d]     = x1 * c1 - x2 * s1;
    p[d + 8] = x2 * c2 + x1 * s2;
}

// ---------------------------------------------------------------------------
// Causal flash attention, fp32. grid = (32 q-tiles, 32 heads), 256 threads.
// 64x64 tiles, 4x4 register tile per thread (tx: 16 col-groups, ty: 16 row-groups).
// Q pre-scaled by 1/sqrt(64). K stored transposed in smem so S-phase loads
// K via float4 (conflict-free).
// ---------------------------------------------------------------------------
__global__ __launch_bounds__(256) void attn_kernel()
{
    extern __shared__ float sm[];
    float* sQ  = sm;               // [64][SP]  (r, d)  pre-scaled
    float* sKT = sm + 64 * SP;     // [64][SP]  (d, c)  transposed
    float* sV  = sm + 2 * 64 * SP; // [64][SP]  (c, d)
    float* sS  = sm + 3 * 64 * SP; // [64][SP]  (r, c)  P values

    const int qi = blockIdx.x;
    const int h  = blockIdx.y;
    const int g = h >> 2, s = h & 3;
    const int qoff = g * 384 + s * 64;
    const int koff = g * 384 + 256;
    const int voff = g * 384 + 320;
    const int q0 = qi * 64;
    const int tid = threadIdx.x;
    const int tx = tid & 15, ty = tid >> 4;

    // load + scale Q tile
    for (int i = tid; i < 64 * 16; i += 256) {
        int r = i >> 4, d4 = (i & 15) << 2;
        float4 v = *(const float4*)(g_qkv + (size_t)(q0 + r) * QKVD + qoff + d4);
        float* p = sQ + r * SP + d4;
        p[0] = v.x * 0.125f; p[1] = v.y * 0.125f;
        p[2] = v.z * 0.125f; p[3] = v.w * 0.125f;
    }

    float m[4], l[4], O[4][4];
#pragma unroll
    for (int i = 0; i < 4; i++) {
        m[i] = -1e30f; l[i] = 0.f;
#pragma unroll
        for (int j = 0; j < 4; j++) O[i][j] = 0.f;
    }

    for (int kt = 0; kt <= qi; kt++) {
        const int k0 = kt * 64;
        // load K (transposed) and V
        for (int i = tid; i < 64 * 16; i += 256) {
            int rr = i >> 4, d4 = (i & 15) << 2;
            const float* base = g_qkv + (size_t)(k0 + rr) * QKVD;
            float4 kv = *(const float4*)(base + koff + d4);
            float4 vv = *(const float4*)(base + voff + d4);
            sKT[(d4 + 0) * SP + rr] = kv.x;
            sKT[(d4 + 1) * SP + rr] = kv.y;
            sKT[(d4 + 2) * SP + rr] = kv.z;
            sKT[(d4 + 3) * SP + rr] = kv.w;
            float* vp = sV + rr * SP + d4;
            vp[0] = vv.x; vp[1] = vv.y; vp[2] = vv.z; vp[3] = vv.w;
        }
        __syncthreads();

        // S = Qs @ K^T
        float acc[4][4];
#pragma unroll
        for (int i = 0; i < 4; i++)
#pragma unroll
            for (int j = 0; j < 4; j++) acc[i][j] = 0.f;

#pragma unroll 4
        for (int d = 0; d < 64; d++) {
            float qreg[4];
#pragma unroll
            for (int i = 0; i < 4; i++) qreg[i] = sQ[(ty * 4 + i) * SP + d];
            float4 kv = *(const float4*)&sKT[d * SP + tx * 4];
            float kreg[4] = {kv.x, kv.y, kv.z, kv.w};
#pragma unroll
            for (int i = 0; i < 4; i++)
#pragma unroll
                for (int j = 0; j < 4; j++)
                    acc[i][j] = fmaf(qreg[i], kreg[j], acc[i][j]);
        }

        // causal mask (only diagonal tile: k0 == q0)
        if (kt == qi) {
#pragma unroll
            for (int i = 0; i < 4; i++)
#pragma unroll
                for (int j = 0; j < 4; j++)
                    if (tx * 4 + j > ty * 4 + i) acc[i][j] = -1e30f;
        }

        // online softmax per row
#pragma unroll
        for (int i = 0; i < 4; i++) {
            float tm = fmaxf(fmaxf(acc[i][0], acc[i][1]), fmaxf(acc[i][2], acc[i][3]));
#pragma unroll
            for (int o = 8; o >= 1; o >>= 1)
                tm = fmaxf(tm, __shfl_xor_sync(0xffffffffu, tm, o, 16));
            float mn = fmaxf(m[i], tm);
            float alpha = __expf(m[i] - mn);
            float p0 = __expf(acc[i][0] - mn);
            float p1 = __expf(acc[i][1] - mn);
            float p2 = __expf(acc[i][2] - mn);
            float p3 = __expf(acc[i][3] - mn);
            float4 pv = make_float4(p0, p1, p2, p3);
            *(float4*)&sS[(ty * 4 + i) * SP + tx * 4] = pv;
            float rs = p0 + p1 + p2 + p3;
#pragma unroll
            for (int o = 8; o >= 1; o >>= 1)
                rs += __shfl_xor_sync(0xffffffffu, rs, o, 16);
            l[i] = l[i] * alpha + rs;
            m[i] = mn;
#pragma unroll
            for (int j = 0; j < 4; j++) O[i][j] *= alpha;
        }
        __syncthreads();

        // O += P @ V
#pragma unroll 4
        for (int c = 0; c < 64; c++) {
            float preg[4];
#pragma unroll
            for (int i = 0; i < 4; i++) preg[i] = sS[(ty * 4 + i) * SP + c];
            float4 vv = *(const float4*)&sV[c * SP + tx * 4];
            float vreg[4] = {vv.x, vv.y, vv.z, vv.w};
#pragma unroll
            for (int i = 0; i < 4; i++)
#pragma unroll
                for (int j = 0; j < 4; j++)
                    O[i][j] = fmaf(preg[i], vreg[j], O[i][j]);
        }
        __syncthreads();
    }

    // write normalized output: yattn[t][h*64 + d]
#pragma unroll
    for (int i = 0; i < 4; i++) {
        float inv = 1.f / l[i];
        float4 o = make_float4(O[i][0] * inv, O[i][1] * inv, O[i][2] * inv, O[i][3] * inv);
        *(float4*)(g_yattn + (size_t)(q0 + ty * 4 + i) * CC + h * 64 + tx * 4) = o;
    }
}

// ---------------------------------------------------------------------------
extern "C" void kernel_launch(void* const* d_in, const int* in_sizes, int n_in,
                              void* d_out, int out_size)
{
    const float* x      = (const float*)d_in[0];
    const float* cosb   = (const float*)d_in[1];
    const float* sinb   = (const float*)d_in[2];
    const float* W_attn = (const float*)d_in[3];
    const float* b_attn = (const float*)d_in[4];
    const float* W_proj = (const float*)d_in[5];
    const float* b_proj = (const float*)d_in[6];
    float* out = (float*)d_out;

    float* qkv = nullptr;
    float* yattn = nullptr;
    cudaGetSymbolAddress((void**)&qkv, g_qkv);
    cudaGetSymbolAddress((void**)&yattn, g_yattn);

    // 1) QKV = x @ W_attn^T + b_attn   (M=2048, N=3072, K=2048)
    sgemm_nt_bias<<<dim3(QKVD / 128, TT / 128), 256>>>(
        x, W_attn, b_attn, qkv, TT, QKVD, CC);

    // 2) RoPE in-place on Q heads + K groups
    rope_kernel<<<(TT * 40 * 8 + 255) / 256, 256>>>(cosb, sinb);

    // 3) causal flash attention -> yattn
    static const int smem_bytes = 4 * 64 * SP * (int)sizeof(float); // 69632
    cudaFuncSetAttribute(attn_kernel, cudaFuncAttributeMaxDynamicSharedMemorySize, smem_bytes);
    attn_kernel<<<dim3(32, 32), 256, smem_bytes>>>();

    // 4) out = yattn @ W_proj^T + b_proj  (M=2048, N=2048, K=2048)
    sgemm_nt_bias<<<dim3(CC / 128, TT / 128), 256>>>(
        yattn, W_proj, b_proj, out, TT, CC, CC);
}

// round 3
// speedup vs baseline: 1.3720x; 1.3720x over previous
#include <cuda_runtime.h>
#include <math.h>

#define TT 2048
#define CC 2048
#define QKVD 3072

__device__ float g_qkv[TT * QKVD];    // [t][3072]
__device__ float g_yattn[TT * CC];    // [t][h*64+d]

// ---------------------------------------------------------------------------
// C[m][n] = sum_k A[m][k]*B[n][k] + bias[n].  128x128 tile, k-step 8,
// 256 threads, 8x8 register tile with split pattern (tx*4 and 64+tx*4) so
// every LDS.128 is a contiguous 256B wavefront-minimal access.
// Register double-buffered global loads.
// ---------------------------------------------------------------------------
__global__ __launch_bounds__(256) void sgemm_nt_bias(
    const float* __restrict__ A, const float* __restrict__ B,
    const float* __restrict__ bias, float* __restrict__ C,
    int M, int N, int K)
{
    __shared__ float As[8][128];
    __shared__ float Bs[8][128];

    const int bm = blockIdx.y * 128;
    const int bn = blockIdx.x * 128;
    const int tid = threadIdx.x;
    const int tx = tid & 15;
    const int ty = tid >> 4;
    const int lr = tid >> 1;       // load row 0..127
    const int lc = (tid & 1) << 2; // k offset 0 or 4

    const float* Aptr = A + (size_t)(bm + lr) * K + lc;
    const float* Bptr = B + (size_t)(bn + lr) * K + lc;

    float4 av = *(const float4*)Aptr;
    float4 bv = *(const float4*)Bptr;

    float acc[8][8];
#pragma unroll
    for (int i = 0; i < 8; i++)
#pragma unroll
        for (int j = 0; j < 8; j++) acc[i][j] = 0.f;

    for (int k0 = 0; k0 < K; k0 += 8) {
        As[lc + 0][lr] = av.x; As[lc + 1][lr] = av.y;
        As[lc + 2][lr] = av.z; As[lc + 3][lr] = av.w;
        Bs[lc + 0][lr] = bv.x; Bs[lc + 1][lr] = bv.y;
        Bs[lc + 2][lr] = bv.z; Bs[lc + 3][lr] = bv.w;
        __syncthreads();

        if (k0 + 8 < K) {
            av = *(const float4*)(Aptr + k0 + 8);
            bv = *(const float4*)(Bptr + k0 + 8);
        }

#pragma unroll
        for (int kk = 0; kk < 8; kk++) {
            float4 a0 = *(const float4*)&As[kk][ty * 4];
            float4 a1 = *(const float4*)&As[kk][ty * 4 + 64];
            float4 b0 = *(const float4*)&Bs[kk][tx * 4];
            float4 b1 = *(const float4*)&Bs[kk][tx * 4 + 64];
            float ra[8] = {a0.x, a0.y, a0.z, a0.w, a1.x, a1.y, a1.z, a1.w};
            float rb[8] = {b0.x, b0.y, b0.z, b0.w, b1.x, b1.y, b1.z, b1.w};
#pragma unroll
            for (int i = 0; i < 8; i++)
#pragma unroll
                for (int j = 0; j < 8; j++)
                    acc[i][j] = fmaf(ra[i], rb[j], acc[i][j]);
        }
        __syncthreads();
    }

#pragma unroll
    for (int ih = 0; ih < 2; ih++)
#pragma unroll
    for (int i = 0; i < 4; i++) {
        const int row = bm + ih * 64 + ty * 4 + i;
#pragma unroll
        for (int jh = 0; jh < 2; jh++) {
            const int col = bn + jh * 64 + tx * 4;
            float4 bsv = *(const float4*)(bias + col);
            float4 o;
            o.x = acc[ih * 4 + i][jh * 4 + 0] + bsv.x;
            o.y = acc[ih * 4 + i][jh * 4 + 1] + bsv.y;
            o.z = acc[ih * 4 + i][jh * 4 + 2] + bsv.z;
            o.w = acc[ih * 4 + i][jh * 4 + 3] + bsv.w;
            *(float4*)(C + (size_t)row * N + col) = o;
        }
    }
}

// ---------------------------------------------------------------------------
// RoPE in-place on first 16 dims of every Q head (32) and K group (8).
// ---------------------------------------------------------------------------
__global__ __launch_bounds__(256) void rope_kernel(
    const float* __restrict__ cosb, const float* __restrict__ sinb)
{
    int idx = blockIdx.x * blockDim.x + threadIdx.x;
    const int total = TT * 40 * 8;
    if (idx >= total) return;
    int d = idx & 7;
    int row = (idx >> 3) % 40;
    int t = idx / (8 * 40);
    int off;
    if (row < 32) { int g = row >> 2, s = row & 3; off = g * 384 + s * 64; }
    else          { int g = row - 32;              off = g * 384 + 256;    }
    float* p = g_qkv + (size_t)t * QKVD + off;
    float x1 = p[d], x2 = p[d + 8];
    float c1 = cosb[t * 16 + d],     s1 = sinb[t * 16 + d];
    float c2 = cosb[t * 16 + d + 8], s2 = sinb[t * 16 + d + 8];
    p[d]     = x1 * c1 - x2 * s1;
    p[d + 8] = x2 * c2 + x1 * s2;
}

// ---------------------------------------------------------------------------
// Flash attention, 128x128 tiles, fp32. 256 threads (16x16), 8x8 S-tile,
// 8x4 O-tile. Q/K transposed+XOR-swizzled in smem; V row-major; P row-major.
// K/V double-buffered through registers.
// ---------------------------------------------------------------------------
#define SWZ(c, d) (((((c) >> 2) ^ (((d) >> 2) & 7)) << 2) | ((c) & 3))

__device__ __forceinline__ void stage_tile(float4* st, int r0, int off)
{
    const int dg = threadIdx.x & 15;
    const int rh = threadIdx.x >> 4;
#pragma unroll
    for (int u = 0; u < 8; u++) {
        int rr = u * 16 + rh;
        st[u] = *(const float4*)(g_qkv + (size_t)(r0 + rr) * QKVD + off + dg * 4);
    }
}

__device__ __forceinline__ void sts_transposed(float* dst, const float4* st)
{
    const int dg = threadIdx.x & 15;
    const int rh = threadIdx.x >> 4;
#pragma unroll
    for (int u = 0; u < 8; u++) {
        int rr = u * 16 + rh;
        int base = SWZ(rr, dg * 4);          // f(d) = dg&7 for all 4 k
        float v[4] = {st[u].x, st[u].y, st[u].z, st[u].w};
#pragma unroll
        for (int k = 0; k < 4; k++)
            dst[(dg * 4 + k) * 128 + base] = v[k];
    }
}

__device__ __forceinline__ void sts_rowmajor_v(float* dst, const float4* st)
{
    const int dg = threadIdx.x & 15;
    const int rh = threadIdx.x >> 4;
#pragma unroll
    for (int u = 0; u < 8; u++) {
        int c = u * 16 + rh;
        *(float4*)&dst[c * 68 + dg * 4] = st[u];
    }
}

__global__ __launch_bounds__(256, 1) void attn_kernel()
{
    extern __shared__ float sm[];
    float* sQT = sm;                     // [64][128] swizzled  (32KB)
    float* sKT = sm + 64 * 128;          // [64][128] swizzled  (32KB)
    float* sV  = sm + 2 * 64 * 128;      // [128][68]           (34KB)
    float* sP  = sm + 2 * 64 * 128 + 128 * 68; // [128][128]    (64KB)

    const int qi = 15 - blockIdx.x;      // long blocks launch first
    const int h  = blockIdx.y;
    const int g = h >> 2, s = h & 3;
    const int qoff = g * 384 + s * 64;
    const int koff = g * 384 + 256;
    const int voff = g * 384 + 320;
    const int q0 = qi * 128;
    const int tid = threadIdx.x;
    const int tx = tid & 15, ty = tid >> 4;

    // row indices owned by this thread (split tile)
    int rix[8];
#pragma unroll
    for (int i = 0; i < 8; i++) rix[i] = (i < 4) ? ty * 4 + i : 64 + ty * 4 + (i - 4);

    float4 stg[8];

    // prologue: Q (scaled) into sQT
    {
        const int dg = tid & 15;
        const int rh = tid >> 4;
#pragma unroll
        for (int u = 0; u < 8; u++) {
            int rr = u * 16 + rh;
            float4 qv = *(const float4*)(g_qkv + (size_t)(q0 + rr) * QKVD + qoff + dg * 4);
            int base = SWZ(rr, dg * 4);
            sQT[(dg * 4 + 0) * 128 + base] = qv.x * 0.125f;
            sQT[(dg * 4 + 1) * 128 + base] = qv.y * 0.125f;
            sQT[(dg * 4 + 2) * 128 + base] = qv.z * 0.125f;
            sQT[(dg * 4 + 3) * 128 + base] = qv.w * 0.125f;
        }
    }
    // prologue: K0, V0
    stage_tile(stg, 0, koff);
    sts_transposed(sKT, stg);
    stage_tile(stg, 0, voff);
    sts_rowmajor_v(sV, stg);
    __syncthreads();

    float m[8], l[8], O[8][4];
#pragma unroll
    for (int i = 0; i < 8; i++) {
        m[i] = -1e30f; l[i] = 0.f;
#pragma unroll
        for (int j = 0; j < 4; j++) O[i][j] = 0.f;
    }

    for (int kt = 0; kt <= qi; kt++) {
        const bool havenext = (kt < qi);
        const int k0n = (havenext ? kt + 1 : kt) * 128;

        // [A] stage next K (latency hidden by S phase)
        stage_tile(stg, k0n, koff);

        // [B] S = Qs @ K^T
        float acc[8][8];
#pragma unroll
        for (int i = 0; i < 8; i++)
#pragma unroll
            for (int j = 0; j < 8; j++) acc[i][j] = 0.f;

#pragma unroll 8
        for (int d = 0; d < 64; d++) {
            const int f4 = ((d >> 2) & 7) << 2;
            const float* qrow = sQT + d * 128;
            const float* krow = sKT + d * 128;
            float4 a0 = *(const float4*)&qrow[(ty * 4) ^ f4];
            float4 a1 = *(const float4*)&qrow[((ty * 4) ^ f4) + 64];
            float4 b0 = *(const float4*)&krow[(tx * 4) ^ f4];
            float4 b1 = *(const float4*)&krow[((tx * 4) ^ f4) + 64];
            float ra[8] = {a0.x, a0.y, a0.z, a0.w, a1.x, a1.y, a1.z, a1.w};
            float rb[8] = {b0.x, b0.y, b0.z, b0.w, b1.x, b1.y, b1.z, b1.w};
#pragma unroll
            for (int i = 0; i < 8; i++)
#pragma unroll
                for (int j = 0; j < 8; j++)
                    acc[i][j] = fmaf(ra[i], rb[j], acc[i][j]);
        }

        // mask diagonal tile
        if (kt == qi) {
#pragma unroll
            for (int i = 0; i < 8; i++) {
#pragma unroll
                for (int j = 0; j < 8; j++) {
                    int cj = (j < 4) ? tx * 4 + j : 64 + tx * 4 + (j - 4);
                    if (cj > rix[i]) acc[i][j] = -1e30f;
                }
            }
        }

        // [C] online softmax, write P
#pragma unroll
        for (int i = 0; i < 8; i++) {
            float rm = acc[i][0];
#pragma unroll
            for (int j = 1; j < 8; j++) rm = fmaxf(rm, acc[i][j]);
#pragma unroll
            for (int o = 8; o >= 1; o >>= 1)
                rm = fmaxf(rm, __shfl_xor_sync(0xffffffffu, rm, o, 16));
            float mn = fmaxf(m[i], rm);
            float alpha = __expf(m[i] - mn);
            float p[8];
            float rs = 0.f;
#pragma unroll
            for (int j = 0; j < 8; j++) { p[j] = __expf(acc[i][j] - mn); rs += p[j]; }
            *(float4*)&sP[rix[i] * 128 + tx * 4]      = make_float4(p[0], p[1], p[2], p[3]);
            *(float4*)&sP[rix[i] * 128 + 64 + tx * 4] = make_float4(p[4], p[5], p[6], p[7]);
#pragma unroll
            for (int o = 8; o >= 1; o >>= 1)
                rs += __shfl_xor_sync(0xffffffffu, rs, o, 16);
            l[i] = l[i] * alpha + rs;
            m[i] = mn;
#pragma unroll
            for (int j = 0; j < 4; j++) O[i][j] *= alpha;
        }
        __syncthreads();   // [D] P visible; K tile reads done

        // [D2] store next K tile (safe: all S reads finished)
        if (havenext) sts_transposed(sKT, stg);

        // [D3] stage next V (latency hidden by PV)
        stage_tile(stg, k0n, voff);

        // [E] O += P @ V
#pragma unroll 2
        for (int c = 0; c < 128; c += 4) {
            float4 pr[8];
#pragma unroll
            for (int i = 0; i < 8; i++)
                pr[i] = *(const float4*)&sP[rix[i] * 128 + c];
#pragma unroll
            for (int cc = 0; cc < 4; cc++) {
                float4 vv = *(const float4*)&sV[(c + cc) * 68 + tx * 4];
                float vr[4] = {vv.x, vv.y, vv.z, vv.w};
#pragma unroll
                for (int i = 0; i < 8; i++) {
                    float pv = ((const float*)&pr[i])[cc];
#pragma unroll
                    for (int j = 0; j < 4; j++)
                        O[i][j] = fmaf(pv, vr[j], O[i][j]);
                }
            }
        }
        __syncthreads();   // [F] V/P reads done

        // [G] store next V
        if (havenext) {
            sts_rowmajor_v(sV, stg);
            __syncthreads(); // [H]
        }
    }

    // write normalized output
#pragma unroll
    for (int i = 0; i < 8; i++) {
        float inv = 1.f / l[i];
        float4 o = make_float4(O[i][0] * inv, O[i][1] * inv, O[i][2] * inv, O[i][3] * inv);
        *(float4*)(g_yattn + (size_t)(q0 + rix[i]) * CC + h * 64 + tx * 4) = o;
    }
}

// ---------------------------------------------------------------------------
extern "C" void kernel_launch(void* const* d_in, const int* in_sizes, int n_in,
                              void* d_out, int out_size)
{
    const float* x      = (const float*)d_in[0];
    const float* cosb   = (const float*)d_in[1];
    const float* sinb   = (const float*)d_in[2];
    const float* W_attn = (const float*)d_in[3];
    const float* b_attn = (const float*)d_in[4];
    const float* W_proj = (const float*)d_in[5];
    const float* b_proj = (const float*)d_in[6];
    float* out = (float*)d_out;

    float* qkv = nullptr;
    float* yattn = nullptr;
    cudaGetSymbolAddress((void**)&qkv, g_qkv);
    cudaGetSymbolAddress((void**)&yattn, g_yattn);

    // 1) QKV = x @ W_attn^T + b_attn
    sgemm_nt_bias<<<dim3(QKVD / 128, TT / 128), 256>>>(
        x, W_attn, b_attn, qkv, TT, QKVD, CC);

    // 2) RoPE
    rope_kernel<<<(TT * 40 * 8 + 255) / 256, 256>>>(cosb, sinb);

    // 3) causal flash attention
    static const int smem_bytes = (2 * 64 * 128 + 128 * 68 + 128 * 128) * (int)sizeof(float);
    cudaFuncSetAttribute(attn_kernel, cudaFuncAttributeMaxDynamicSharedMemorySize, smem_bytes);
    attn_kernel<<<dim3(16, 32), 256, smem_bytes>>>();

    // 4) out = yattn @ W_proj^T + b_proj
    sgemm_nt_bias<<<dim3(CC / 128, TT / 128), 256>>>(
        yattn, W_proj, b_proj, out, TT, CC, CC);
}